// round 3
// baseline (speedup 1.0000x reference)
#include <cuda_runtime.h>
#include <math.h>

// Problem constants
#define BATCH   4
#define C_UV    14
#define HW_IN   (512 * 512)          // gaussians per batch
#define W_OUT   1024
#define HW_OUT  (1024 * 1024)
#define N_GAUSS (BATCH * HW_IN)      // 1,048,576
#define OUT_ELEMS (BATCH * 3 * HW_OUT)

// ---------------------------------------------------------------------------
// Kernel 1: zero the framebuffer (d_out is poisoned to 0xAA by the harness)
// ---------------------------------------------------------------------------
__global__ void gr_zero_kernel(float4* __restrict__ out, int n4) {
    int i = blockIdx.x * blockDim.x + threadIdx.x;
    if (i < n4) out[i] = make_float4(0.f, 0.f, 0.f, 0.f);
}

// ---------------------------------------------------------------------------
// Kernel 2: scatter-add gaussians.
// One thread per gaussian. Reads are per-channel coalesced (consecutive
// threads -> consecutive n within a channel plane). atomicAdd return unused
// -> REDG (no return latency).
// ---------------------------------------------------------------------------
__global__ void gr_scatter_kernel(const float* __restrict__ uv,
                                  const float* __restrict__ pos,
                                  float* __restrict__ out) {
    int gid = blockIdx.x * blockDim.x + threadIdx.x;
    if (gid >= N_GAUSS) return;
    int b = gid >> 18;            // / HW_IN (262144 = 2^18)
    int n = gid & (HW_IN - 1);

    const float* uvb  = uv  + (size_t)b * C_UV * HW_IN;
    const float* posb = pos + (size_t)b * 3 * HW_IN;

    // position xy = position_map + uv_maps[0:2]  (z / channel 2 unused)
    float x = posb[n]           + uvb[n];
    float y = posb[HW_IN + n]   + uvb[HW_IN + n];

    // opacity = sigmoid(uv ch 10)
    float o = uvb[10 * HW_IN + n];
    o = 1.0f / (1.0f + expf(-o));

    // colors = uv ch 11..13, premultiplied by opacity
    float r  = uvb[11 * HW_IN + n] * o;
    float g  = uvb[12 * HW_IN + n] * o;
    float bl = uvb[13 * HW_IN + n] * o;

    // NDC -> integer pixel, truncating cast then clamp (matches .astype(int32) + clip)
    int px = (int)((x + 1.0f) * 0.5f * (float)W_OUT);
    int py = (int)((y + 1.0f) * 0.5f * (float)W_OUT);
    px = min(max(px, 0), W_OUT - 1);
    py = min(max(py, 0), W_OUT - 1);
    int idx = py * W_OUT + px;

    float* ob = out + (size_t)b * 3 * HW_OUT;
    atomicAdd(ob + idx,              r);
    atomicAdd(ob + HW_OUT + idx,     g);
    atomicAdd(ob + 2 * HW_OUT + idx, bl);
}

// ---------------------------------------------------------------------------
// Kernel 3: clamp framebuffer to [0, 1]
// ---------------------------------------------------------------------------
__global__ void gr_clamp_kernel(float4* __restrict__ out, int n4) {
    int i = blockIdx.x * blockDim.x + threadIdx.x;
    if (i < n4) {
        float4 v = out[i];
        v.x = __saturatef(v.x);
        v.y = __saturatef(v.y);
        v.z = __saturatef(v.z);
        v.w = __saturatef(v.w);
        out[i] = v;
    }
}

// ---------------------------------------------------------------------------
extern "C" void kernel_launch(void* const* d_in, const int* in_sizes, int n_in,
                              void* d_out, int out_size) {
    const float* uv  = (const float*)d_in[0];   // [4,14,512,512]
    const float* pos = (const float*)d_in[1];   // [4,3,512,512]
    float* out = (float*)d_out;                 // [4,3,1024,1024]

    const int n4 = OUT_ELEMS / 4;               // 3,145,728 float4s
    const int TPB = 256;

    gr_zero_kernel<<<(n4 + TPB - 1) / TPB, TPB>>>((float4*)out, n4);
    gr_scatter_kernel<<<(N_GAUSS + TPB - 1) / TPB, TPB>>>(uv, pos, out);
    gr_clamp_kernel<<<(n4 + TPB - 1) / TPB, TPB>>>((float4*)out, n4);
}

// round 4
// speedup vs baseline: 1.7406x; 1.7406x over previous
#include <cuda_runtime.h>
#include <math.h>

// Problem constants
#define BATCH    4
#define HW_IN    (512 * 512)         // gaussians per batch (2^18)
#define W_OUT    1024
#define HW_OUT   (1024 * 1024)
#define N_GAUSS  (BATCH * HW_IN)     // 1,048,576
#define OUT_ELEMS (BATCH * 3 * HW_OUT)

// Border privatization: 73% of gaussians clamp to the 1-pixel border ring;
// corners each take ~5.7% of a batch (~15k same-address atomics). Replicate
// a compact border accumulator R ways to kill LTS atomic serialization.
#define R_REP    64
#define BI_N     4096                        // compact border slots per (b,c)
#define REP_STRIDE (BATCH * 3 * BI_N)        // floats per replica
#define SCRATCH_FLOATS (R_REP * REP_STRIDE)  // 12.58 MB

__device__ float g_border[SCRATCH_FLOATS];

#define N4_OUT     (OUT_ELEMS / 4)           // 3,145,728
#define N4_SCRATCH (SCRATCH_FLOATS / 4)      //   786,432

// ---------------------------------------------------------------------------
// Kernel 1: zero framebuffer + border scratch
// ---------------------------------------------------------------------------
__global__ void gr_zero_kernel(float4* __restrict__ out) {
    int i = blockIdx.x * blockDim.x + threadIdx.x;
    float4 z = make_float4(0.f, 0.f, 0.f, 0.f);
    if (i < N4_OUT) {
        out[i] = z;
    } else if (i < N4_OUT + N4_SCRATCH) {
        reinterpret_cast<float4*>(g_border)[i - N4_OUT] = z;
    }
}

// ---------------------------------------------------------------------------
// Kernel 2: scatter. Interior pixels -> direct atomics (spread, fast).
// Border pixels -> replicated compact accumulator (replica = block % 64).
// ---------------------------------------------------------------------------
__global__ void gr_scatter_kernel(const float* __restrict__ uv,
                                  const float* __restrict__ pos,
                                  float* __restrict__ out) {
    int gid = blockIdx.x * blockDim.x + threadIdx.x;
    if (gid >= N_GAUSS) return;
    int b = gid >> 18;            // / HW_IN
    int n = gid & (HW_IN - 1);

    const float* uvb  = uv  + (size_t)b * 14 * HW_IN;
    const float* posb = pos + (size_t)b * 3 * HW_IN;

    float x = posb[n]         + uvb[n];
    float y = posb[HW_IN + n] + uvb[HW_IN + n];

    float o = uvb[10 * HW_IN + n];
    o = 1.0f / (1.0f + expf(-o));

    float r  = uvb[11 * HW_IN + n] * o;
    float g  = uvb[12 * HW_IN + n] * o;
    float bl = uvb[13 * HW_IN + n] * o;

    // truncating cast then clamp (matches .astype(int32) + clip)
    int px = (int)((x + 1.0f) * 0.5f * (float)W_OUT);
    int py = (int)((y + 1.0f) * 0.5f * (float)W_OUT);
    px = min(max(px, 0), W_OUT - 1);
    py = min(max(py, 0), W_OUT - 1);

    bool border = (px == 0) | (px == W_OUT - 1) | (py == 0) | (py == W_OUT - 1);
    if (border) {
        // compact border index:
        //   py==0    -> [0,1024)    : px
        //   py==1023 -> [1024,2048) : 1024+px
        //   px==0    -> 2048+py   (py in 1..1022)
        //   px==1023 -> 3072+py
        int bi = (py == 0)         ? px
               : (py == W_OUT - 1) ? (1024 + px)
               : (px == 0)         ? (2048 + py)
                                   : (3072 + py);
        int rep = blockIdx.x & (R_REP - 1);
        float* s = g_border + (size_t)rep * REP_STRIDE + (size_t)(b * 3) * BI_N;
        atomicAdd(s + bi,            r);
        atomicAdd(s + BI_N + bi,     g);
        atomicAdd(s + 2 * BI_N + bi, bl);
    } else {
        int idx = py * W_OUT + px;
        float* ob = out + (size_t)b * 3 * HW_OUT;
        atomicAdd(ob + idx,              r);
        atomicAdd(ob + HW_OUT + idx,     g);
        atomicAdd(ob + 2 * HW_OUT + idx, bl);
    }
}

// ---------------------------------------------------------------------------
// Kernel 3: fused border-reduce + clamp.
// One thread per output float4. Border float4s gather the 64 replica sums
// (border pixels receive contributions ONLY via the privatized path, so a
// plain add is race-free), then everything is saturated to [0,1].
// ---------------------------------------------------------------------------
__global__ void gr_reduce_clamp_kernel(float4* __restrict__ out) {
    int i = blockIdx.x * blockDim.x + threadIdx.x;
    if (i >= N4_OUT) return;

    int pc  = i >> 18;          // (b*3 + c): 262144 float4 per plane
    int e   = i & 0x3FFFF;
    int row  = e >> 8;          // 256 float4 per row
    int col4 = e & 255;

    float4 v = out[i];
    const float* s = g_border + (size_t)pc * BI_N;

    if (row == 0 || row == W_OUT - 1) {
        int bi = ((row == W_OUT - 1) ? 1024 : 0) + (col4 << 2);
        float a0 = 0.f, a1 = 0.f, a2 = 0.f, a3 = 0.f;
        #pragma unroll 8
        for (int rp = 0; rp < R_REP; ++rp) {
            float4 sv = *reinterpret_cast<const float4*>(s + (size_t)rp * REP_STRIDE + bi);
            a0 += sv.x; a1 += sv.y; a2 += sv.z; a3 += sv.w;
        }
        v.x += a0; v.y += a1; v.z += a2; v.w += a3;
    } else if (col4 == 0) {
        int bi = 2048 + row;
        float a = 0.f;
        #pragma unroll 8
        for (int rp = 0; rp < R_REP; ++rp) a += s[(size_t)rp * REP_STRIDE + bi];
        v.x += a;
    } else if (col4 == 255) {
        int bi = 3072 + row;
        float a = 0.f;
        #pragma unroll 8
        for (int rp = 0; rp < R_REP; ++rp) a += s[(size_t)rp * REP_STRIDE + bi];
        v.w += a;
    }

    v.x = __saturatef(v.x);
    v.y = __saturatef(v.y);
    v.z = __saturatef(v.z);
    v.w = __saturatef(v.w);
    out[i] = v;
}

// ---------------------------------------------------------------------------
extern "C" void kernel_launch(void* const* d_in, const int* in_sizes, int n_in,
                              void* d_out, int out_size) {
    const float* uv  = (const float*)d_in[0];   // [4,14,512,512]
    const float* pos = (const float*)d_in[1];   // [4,3,512,512]
    float* out = (float*)d_out;                 // [4,3,1024,1024]

    const int TPB = 256;
    const int n4_total = N4_OUT + N4_SCRATCH;

    gr_zero_kernel<<<(n4_total + TPB - 1) / TPB, TPB>>>((float4*)out);
    gr_scatter_kernel<<<(N_GAUSS + TPB - 1) / TPB, TPB>>>(uv, pos, out);
    gr_reduce_clamp_kernel<<<(N4_OUT + TPB - 1) / TPB, TPB>>>((float4*)out);
}

// round 5
// speedup vs baseline: 3.0834x; 1.7714x over previous
#include <cuda_runtime.h>
#include <math.h>

// Problem constants
#define BATCH    4
#define HW_IN    (512 * 512)         // gaussians per batch (2^18)
#define W_OUT    1024
#define HW_OUT   (1024 * 1024)
#define N_GAUSS  (BATCH * HW_IN)     // 1,048,576
#define OUT_ELEMS (BATCH * 3 * HW_OUT)

// Border privatization: ~73% of gaussians clamp onto the 1-pixel border ring.
// Channel-interleaved replicated accumulator: one red.v4 per border gaussian.
#define R_REP    32
#define BI_N     4096                          // compact border slots per batch
// g_border layout: [rep][b][bi] -> float4 (r,g,b,unused)
__device__ float4 g_border[R_REP * BATCH * BI_N];          // 8 MB
// g_bsum layout:   [b][bi] -> float4 (replica-reduced)
__device__ float4 g_bsum[BATCH * BI_N];                    // 256 KB

#define N4_OUT      (OUT_ELEMS / 4)            // 3,145,728
#define N4_SCRATCH  (R_REP * BATCH * BI_N)     //   524,288

// ---------------------------------------------------------------------------
// Kernel 1: zero framebuffer + border scratch
// ---------------------------------------------------------------------------
__global__ void gr_zero_kernel(float4* __restrict__ out) {
    int i = blockIdx.x * blockDim.x + threadIdx.x;
    float4 z = make_float4(0.f, 0.f, 0.f, 0.f);
    if (i < N4_OUT) {
        out[i] = z;
    } else if (i < N4_OUT + N4_SCRATCH) {
        g_border[i - N4_OUT] = z;
    }
}

// ---------------------------------------------------------------------------
// Kernel 2: scatter. Interior -> direct scalar atomics (spread, cheap).
// Border -> one red.global.add.v4.f32 into replicated interleaved scratch.
// ---------------------------------------------------------------------------
__global__ void gr_scatter_kernel(const float* __restrict__ uv,
                                  const float* __restrict__ pos,
                                  float* __restrict__ out) {
    int gid = blockIdx.x * blockDim.x + threadIdx.x;
    if (gid >= N_GAUSS) return;
    int b = gid >> 18;            // / HW_IN
    int n = gid & (HW_IN - 1);

    const float* uvb  = uv  + (size_t)b * 14 * HW_IN;
    const float* posb = pos + (size_t)b * 3 * HW_IN;

    // batch the 8 loads for MLP
    float p0 = posb[n];
    float p1 = posb[HW_IN + n];
    float u0 = uvb[n];
    float u1 = uvb[HW_IN + n];
    float uo = uvb[10 * HW_IN + n];
    float c0 = uvb[11 * HW_IN + n];
    float c1 = uvb[12 * HW_IN + n];
    float c2 = uvb[13 * HW_IN + n];

    float x = p0 + u0;
    float y = p1 + u1;
    float o = 1.0f / (1.0f + expf(-uo));
    float r  = c0 * o;
    float g  = c1 * o;
    float bl = c2 * o;

    // truncating cast then clamp (matches .astype(int32) + clip)
    int px = (int)((x + 1.0f) * 0.5f * (float)W_OUT);
    int py = (int)((y + 1.0f) * 0.5f * (float)W_OUT);
    px = min(max(px, 0), W_OUT - 1);
    py = min(max(py, 0), W_OUT - 1);

    bool border = (px == 0) | (px == W_OUT - 1) | (py == 0) | (py == W_OUT - 1);
    if (border) {
        // compact border index:
        //   py==0    -> px            [0,1024)
        //   py==1023 -> 1024+px       [1024,2048)
        //   px==0    -> 2048+py       (py in 1..1022)
        //   px==1023 -> 3072+py
        int bi = (py == 0)         ? px
               : (py == W_OUT - 1) ? (1024 + px)
               : (px == 0)         ? (2048 + py)
                                   : (3072 + py);
        int rep = ((blockIdx.x << 3) | (threadIdx.x >> 5)) & (R_REP - 1);
        float* p = (float*)&g_border[(rep * BATCH + b) * BI_N + bi];
        asm volatile("red.global.add.v4.f32 [%0], {%1, %2, %3, %4};"
                     :: "l"(p), "f"(r), "f"(g), "f"(bl), "f"(0.0f)
                     : "memory");
    } else {
        int idx = py * W_OUT + px;
        float* ob = out + (size_t)b * 3 * HW_OUT;
        atomicAdd(ob + idx,              r);
        atomicAdd(ob + HW_OUT + idx,     g);
        atomicAdd(ob + 2 * HW_OUT + idx, bl);
    }
}

// ---------------------------------------------------------------------------
// Kernel 3: collapse the R_REP replicas -> g_bsum. 16384 threads, one slot each.
// ---------------------------------------------------------------------------
__global__ void gr_repreduce_kernel() {
    int t = blockIdx.x * blockDim.x + threadIdx.x;   // [0, BATCH*BI_N)
    if (t >= BATCH * BI_N) return;
    float a0 = 0.f, a1 = 0.f, a2 = 0.f;
    #pragma unroll 8
    for (int rp = 0; rp < R_REP; ++rp) {
        float4 v = g_border[rp * BATCH * BI_N + t];
        a0 += v.x; a1 += v.y; a2 += v.z;
    }
    g_bsum[t] = make_float4(a0, a1, a2, 0.f);
}

// ---------------------------------------------------------------------------
// Kernel 4: fused border-add + clamp. Border pixels receive contributions ONLY
// via the privatized path, so plain add is race-free; each border lane now
// reads a single pre-reduced value.
// ---------------------------------------------------------------------------
__global__ void gr_final_kernel(float4* __restrict__ out) {
    int i = blockIdx.x * blockDim.x + threadIdx.x;
    if (i >= N4_OUT) return;

    int pc   = i >> 18;          // b*3 + c  (262144 float4 per plane)
    int e    = i & 0x3FFFF;
    int row  = e >> 8;           // 256 float4 per row
    int col4 = e & 255;
    int b = pc / 3;
    int c = pc - 3 * b;

    float4 v = out[i];
    const float* gb = (const float*)(g_bsum + b * BI_N);   // [bi][4]

    if (row == 0) {
        int px0 = col4 << 2;
        v.x += gb[(px0 + 0) * 4 + c];
        v.y += gb[(px0 + 1) * 4 + c];
        v.z += gb[(px0 + 2) * 4 + c];
        v.w += gb[(px0 + 3) * 4 + c];
    } else if (row == W_OUT - 1) {
        int bi0 = 1024 + (col4 << 2);
        v.x += gb[(bi0 + 0) * 4 + c];
        v.y += gb[(bi0 + 1) * 4 + c];
        v.z += gb[(bi0 + 2) * 4 + c];
        v.w += gb[(bi0 + 3) * 4 + c];
    } else if (col4 == 0) {
        v.x += gb[(2048 + row) * 4 + c];
    } else if (col4 == 255) {
        v.w += gb[(3072 + row) * 4 + c];
    }

    v.x = __saturatef(v.x);
    v.y = __saturatef(v.y);
    v.z = __saturatef(v.z);
    v.w = __saturatef(v.w);
    out[i] = v;
}

// ---------------------------------------------------------------------------
extern "C" void kernel_launch(void* const* d_in, const int* in_sizes, int n_in,
                              void* d_out, int out_size) {
    const float* uv  = (const float*)d_in[0];   // [4,14,512,512]
    const float* pos = (const float*)d_in[1];   // [4,3,512,512]
    float* out = (float*)d_out;                 // [4,3,1024,1024]

    const int TPB = 256;
    const int n4_total = N4_OUT + N4_SCRATCH;

    gr_zero_kernel<<<(n4_total + TPB - 1) / TPB, TPB>>>((float4*)out);
    gr_scatter_kernel<<<(N_GAUSS + TPB - 1) / TPB, TPB>>>(uv, pos, out);
    gr_repreduce_kernel<<<(BATCH * BI_N + TPB - 1) / TPB, TPB>>>();
    gr_final_kernel<<<(N4_OUT + TPB - 1) / TPB, TPB>>>((float4*)out);
}